// round 3
// baseline (speedup 1.0000x reference)
#include <cuda_runtime.h>
#include <cuda_bf16.h>
#include <cstdint>

// ---------------------------------------------------------------------------
// SparseTransformerBlock — Round 3: tf32 mma.sync GEMM with double-buffered
// SMEM, one barrier per BK iteration (STS overlapped with MMA on other buf).
// ---------------------------------------------------------------------------

#define NTOK 16384
#define CDIM 1024
#define HEADS 16
#define HDIM 64
#define WS 512
#define SHIFTK 256
#define MVD4 4096
#define KCAT 9216
#define HID 4096
#define NZ 512

__device__ float g_lnx  [(long)NTOK * CDIM];
__device__ float g_qkv  [(long)NTOK * 3 * CDIM];
__device__ float g_scores[(long)NZ * WS * WS];
__device__ float g_attn [(long)NTOK * CDIM];
__device__ float g_x1   [(long)NTOK * CDIM];
__device__ float g_x2   [(long)NTOK * CDIM];
__device__ float g_lnb  [(long)NTOK * CDIM];
__device__ float g_h1   [(long)NTOK * HID];

// ---------------------------------------------------------------------------
__global__ __launch_bounds__(256) void ln_kernel(const float* __restrict__ in,
                                                 float* __restrict__ out,
                                                 int shift) {
    int row = blockIdx.x;
    int src = (row + shift) & (NTOK - 1);
    const float* p = in + (long)src * CDIM;
    int t = threadIdx.x;
    float v[4], s = 0.f, s2 = 0.f;
#pragma unroll
    for (int i = 0; i < 4; i++) {
        v[i] = p[t + i * 256];
        s += v[i]; s2 += v[i] * v[i];
    }
#pragma unroll
    for (int o = 16; o; o >>= 1) {
        s  += __shfl_xor_sync(~0u, s, o);
        s2 += __shfl_xor_sync(~0u, s2, o);
    }
    __shared__ float red0[8], red1[8];
    int wid = t >> 5, lid = t & 31;
    if (lid == 0) { red0[wid] = s; red1[wid] = s2; }
    __syncthreads();
    if (t < 32) {
        float a = (t < 8) ? red0[t] : 0.f;
        float b = (t < 8) ? red1[t] : 0.f;
#pragma unroll
        for (int o = 4; o; o >>= 1) {
            a += __shfl_xor_sync(~0u, a, o);
            b += __shfl_xor_sync(~0u, b, o);
        }
        if (t == 0) { red0[0] = a; red1[0] = b; }
    }
    __syncthreads();
    float mean = red0[0] * (1.f / CDIM);
    float var  = red1[0] * (1.f / CDIM) - mean * mean;
    float r = rsqrtf(var + 1e-6f);
    float* q = out + (long)row * CDIM;
#pragma unroll
    for (int i = 0; i < 4; i++) q[t + i * 256] = (v[i] - mean) * r;
}

// ---------------------------------------------------------------------------
__global__ __launch_bounds__(256) void softmax_kernel(float* __restrict__ sc) {
    float* p = sc + (long)blockIdx.x * WS;
    int t = threadIdx.x;
    float a = p[t], b = p[t + 256];
    float mx = fmaxf(a, b);
    __shared__ float red[8];
    int wid = t >> 5, lid = t & 31;
#pragma unroll
    for (int o = 16; o; o >>= 1) mx = fmaxf(mx, __shfl_xor_sync(~0u, mx, o));
    if (lid == 0) red[wid] = mx;
    __syncthreads();
    if (t < 32) {
        float v = (t < 8) ? red[t] : -1e30f;
#pragma unroll
        for (int o = 4; o; o >>= 1) v = fmaxf(v, __shfl_xor_sync(~0u, v, o));
        if (t == 0) red[0] = v;
    }
    __syncthreads();
    mx = red[0];
    float ea = __expf(a - mx), eb = __expf(b - mx);
    float sum = ea + eb;
#pragma unroll
    for (int o = 16; o; o >>= 1) sum += __shfl_xor_sync(~0u, sum, o);
    __shared__ float red2[8];
    if (lid == 0) red2[wid] = sum;
    __syncthreads();
    if (t < 32) {
        float v = (t < 8) ? red2[t] : 0.f;
#pragma unroll
        for (int o = 4; o; o >>= 1) v += __shfl_xor_sync(~0u, v, o);
        if (t == 0) red2[0] = v;
    }
    __syncthreads();
    float inv = __frcp_rn(red2[0]);
    p[t] = ea * inv;
    p[t + 256] = eb * inv;
}

__device__ __forceinline__ float gelu_tanh(float v) {
    return 0.5f * v * (1.f + tanhf(0.7978845608028654f * (v + 0.044715f * v * v * v)));
}

__device__ __forceinline__ unsigned tf32r(float f) {
    unsigned r; asm("cvt.rna.tf32.f32 %0, %1;" : "=r"(r) : "f"(f)); return r;
}

#define MMA_TF32(c, a0, a1, a2, a3, b0, b1)                                   \
    asm volatile("mma.sync.aligned.m16n8k8.row.col.f32.tf32.tf32.f32 "        \
                 "{%0,%1,%2,%3},{%4,%5,%6,%7},{%8,%9},{%0,%1,%2,%3};"         \
                 : "+f"((c)[0]), "+f"((c)[1]), "+f"((c)[2]), "+f"((c)[3])     \
                 : "r"(a0), "r"(a1), "r"(a2), "r"(a3), "r"(b0), "r"(b1))

// ---------------------------------------------------------------------------
// tf32 tensor-core GEMM, double-buffered SMEM, 1 barrier/iter.
// BM=BN=128, BK=16, 256 threads (2x4 warps), warp tile 64x32.
// SMEM rows k-permuted: pk = (k&3)*4 + (k>>2), row stride 20 words.
// ---------------------------------------------------------------------------
#define BM 128
#define BN 128
#define BK 16
#define SROW 20

__global__ __launch_bounds__(256, 2) void gemm_tc(
    const float* __restrict__ A0, const float* __restrict__ A1,
    const float* __restrict__ A2, int kb1, int kb2,
    int lda0, int lda1, int lda2,
    const float* __restrict__ B, int ldb, int btrans,
    float* __restrict__ C, int ldc,
    const float* __restrict__ bias, const float* __restrict__ resid,
    int M, int N, int K, float alpha, int epi, int rowShift,
    long aZw, long aZh, long bZw, long bZh, long cZw, long cZh)
{
    __shared__ unsigned As[2][BM * SROW];
    __shared__ unsigned Bs[2][BN * SROW];

    const int z = blockIdx.z, w = z >> 4, hh = z & 15;
    const float* Ab = A0 + (long)w * aZw + (long)hh * aZh;
    const float* Bb = B  + (long)w * bZw + (long)hh * bZh;
    float*       Cb = C  + (long)w * cZw + (long)hh * cZh;

    const int tid = threadIdx.x, lane = tid & 31, wid = tid >> 5;
    const int wm = wid >> 2, wn = wid & 3;
    const int g = lane >> 2, t4 = lane & 3;
    const int m0 = blockIdx.y * BM, n0 = blockIdx.x * BN;

    float acc[4][4][4];
#pragma unroll
    for (int i = 0; i < 4; i++)
#pragma unroll
        for (int j = 0; j < 4; j++)
#pragma unroll
            for (int r = 0; r < 4; r++) acc[i][j][r] = 0.f;

    const int aM = tid >> 1;          // 0..127
    const int aH = (tid & 1) << 3;    // 0 or 8
    const int bn0i = tid & 127;
    const int bc0 = tid >> 7;

    float4 sa0, sa1, sb0, sb1;

    auto LOAD = [&](int k0) {
        {
            int gk = k0 + aH;
            const float* p;
            if (gk < kb1)      p = Ab + (long)(m0 + aM) * lda0 + gk;
            else if (gk < kb2) p = A1 + (long)(m0 + aM) * lda1 + (gk - kb1);
            else               p = A2 + (long)(m0 + aM) * lda2 + (gk - kb2);
            sa0 = *(const float4*)p;
            sa1 = *(const float4*)(p + 4);
        }
        if (btrans) {
            const float* p = Bb + (long)(n0 + aM) * ldb + k0 + aH;
            sb0 = *(const float4*)p;
            sb1 = *(const float4*)(p + 4);
        } else {
            int gn = n0 + bn0i;
            float v0[4], v1[4];
#pragma unroll
            for (int r = 0; r < 4; r++) {
                int gk0 = k0 + bc0 + 4 * r;
                int gk1 = k0 + bc0 + 2 + 4 * r;
                v0[r] = (gn < N) ? Bb[(long)gk0 * ldb + gn] : 0.f;
                v1[r] = (gn < N) ? Bb[(long)gk1 * ldb + gn] : 0.f;
            }
            sb0 = make_float4(v0[0], v0[1], v0[2], v0[3]);
            sb1 = make_float4(v1[0], v1[1], v1[2], v1[3]);
        }
    };

    auto STORE = [&](unsigned* Ad, unsigned* Bd) {
        unsigned* ap = Ad + aM * SROW;
        float av[8] = {sa0.x, sa0.y, sa0.z, sa0.w, sa1.x, sa1.y, sa1.z, sa1.w};
#pragma unroll
        for (int j = 0; j < 8; j++) {
            int k = aH + j;
            ap[((k & 3) << 2) | (k >> 2)] = tf32r(av[j]);
        }
        if (btrans) {
            unsigned* bp = Bd + aM * SROW;
            float bv[8] = {sb0.x, sb0.y, sb0.z, sb0.w, sb1.x, sb1.y, sb1.z, sb1.w};
#pragma unroll
            for (int j = 0; j < 8; j++) {
                int k = aH + j;
                bp[((k & 3) << 2) | (k >> 2)] = tf32r(bv[j]);
            }
        } else {
            uint4 u0 = {tf32r(sb0.x), tf32r(sb0.y), tf32r(sb0.z), tf32r(sb0.w)};
            uint4 u1 = {tf32r(sb1.x), tf32r(sb1.y), tf32r(sb1.z), tf32r(sb1.w)};
            *(uint4*)&Bd[bn0i * SROW + (bc0 << 2)]       = u0;
            *(uint4*)&Bd[bn0i * SROW + ((bc0 + 2) << 2)] = u1;
        }
    };

    auto COMPUTE = [&](const unsigned* Ad, const unsigned* Bd) {
        uint4 bf[4];
#pragma unroll
        for (int j = 0; j < 4; j++)
            bf[j] = *(const uint4*)&Bd[(wn * 32 + j * 8 + g) * SROW + (t4 << 2)];
#pragma unroll
        for (int i = 0; i < 4; i++) {
            int r = wm * 64 + i * 16 + g;
            uint4 lo = *(const uint4*)&Ad[r * SROW + (t4 << 2)];
            uint4 hi = *(const uint4*)&Ad[(r + 8) * SROW + (t4 << 2)];
#pragma unroll
            for (int j = 0; j < 4; j++) {
                MMA_TF32(acc[i][j], lo.x, hi.x, lo.y, hi.y, bf[j].x, bf[j].y);
                MMA_TF32(acc[i][j], lo.z, hi.z, lo.w, hi.w, bf[j].z, bf[j].w);
            }
        }
    };

    const int T = K / BK;
    LOAD(0);
    STORE(As[0], Bs[0]);
    if (T > 1) LOAD(BK);
    __syncthreads();
    for (int t = 0; t < T; t++) {
        int cur = t & 1;
        if (t + 1 < T) STORE(As[cur ^ 1], Bs[cur ^ 1]);   // regs hold tile t+1
        if (t + 2 < T) LOAD((t + 2) * BK);
        COMPUTE(As[cur], Bs[cur]);
        __syncthreads();
    }

    // ---- epilogue ----
#pragma unroll
    for (int i = 0; i < 4; i++) {
        int mr = m0 + wm * 64 + i * 16 + g;
        int r0 = rowShift ? ((mr + rowShift) & (NTOK - 1)) : mr;
        int r1 = rowShift ? ((mr + 8 + rowShift) & (NTOK - 1)) : (mr + 8);
#pragma unroll
        for (int j = 0; j < 4; j++) {
            int col = n0 + wn * 32 + j * 8 + (t4 << 1);
            if (col >= N) continue;
            float b0 = bias ? bias[col]     : 0.f;
            float b1 = bias ? bias[col + 1] : 0.f;
            float v00 = acc[i][j][0] * alpha + b0;
            float v01 = acc[i][j][1] * alpha + b1;
            float v10 = acc[i][j][2] * alpha + b0;
            float v11 = acc[i][j][3] * alpha + b1;
            if (epi == 1) {
                v00 = gelu_tanh(v00); v01 = gelu_tanh(v01);
                v10 = gelu_tanh(v10); v11 = gelu_tanh(v11);
            } else if (epi == 2) {
                const float* q0 = resid + (long)r0 * ldc + col;
                const float* q1 = resid + (long)r1 * ldc + col;
                v00 += q0[0]; v01 += q0[1];
                v10 += q1[0]; v11 += q1[1];
            }
            *(float2*)(Cb + (long)r0 * ldc + col) = make_float2(v00, v01);
            *(float2*)(Cb + (long)r1 * ldc + col) = make_float2(v10, v11);
        }
    }
}

// ---------------------------------------------------------------------------
extern "C" void kernel_launch(void* const* d_in, const int* in_sizes, int n_in,
                              void* d_out, int out_size) {
    const float* x      = (const float*)d_in[0];
    const float* mvn    = (const float*)d_in[1];
    const float* mvc    = (const float*)d_in[2];
    const float* qkv_w  = (const float*)d_in[3];
    const float* qkv_b  = (const float*)d_in[4];
    const float* proj_w = (const float*)d_in[5];
    const float* proj_b = (const float*)d_in[6];
    const float* mv_w1  = (const float*)d_in[7];
    const float* mv_b1  = (const float*)d_in[8];
    const float* mv_w2  = (const float*)d_in[9];
    const float* mv_b2  = (const float*)d_in[10];
    const float* mlp_w1 = (const float*)d_in[11];
    const float* mlp_b1 = (const float*)d_in[12];
    const float* mlp_w2 = (const float*)d_in[13];
    const float* mlp_b2 = (const float*)d_in[14];
    float* out = (float*)d_out;

    float *lnx, *qkv, *scores, *attn, *x1, *x2, *lnb, *h1;
    cudaGetSymbolAddress((void**)&lnx,    g_lnx);
    cudaGetSymbolAddress((void**)&qkv,    g_qkv);
    cudaGetSymbolAddress((void**)&scores, g_scores);
    cudaGetSymbolAddress((void**)&attn,   g_attn);
    cudaGetSymbolAddress((void**)&x1,     g_x1);
    cudaGetSymbolAddress((void**)&x2,     g_x2);
    cudaGetSymbolAddress((void**)&lnb,    g_lnb);
    cudaGetSymbolAddress((void**)&h1,     g_h1);

    // 1) lnx[j] = LN(x[(j+SHIFT)%N])
    ln_kernel<<<NTOK, 256>>>(x, lnx, SHIFTK);

    // 2) qkv = lnx @ qkv_w + qkv_b
    gemm_tc<<<dim3(3 * CDIM / BN, NTOK / BM, 1), 256>>>(
        lnx, nullptr, nullptr, CDIM, CDIM, CDIM, 0, 0,
        qkv_w, 3 * CDIM, 0, qkv, 3 * CDIM, qkv_b, nullptr,
        NTOK, 3 * CDIM, CDIM, 1.f, 0, 0, 0, 0, 0, 0, 0, 0);

    // 3) scores = Q K^T / 8 per (window, head)
    gemm_tc<<<dim3(WS / BN, WS / BM, NZ), 256>>>(
        qkv, nullptr, nullptr, HDIM, HDIM, 3 * CDIM, 0, 0,
        qkv + CDIM, 3 * CDIM, 1, scores, WS, nullptr, nullptr,
        WS, WS, HDIM, 0.125f, 0, 0,
        (long)WS * 3 * CDIM, HDIM,
        (long)WS * 3 * CDIM, HDIM,
        (long)WS * WS * HEADS, (long)WS * WS);

    // 4) softmax
    softmax_kernel<<<NZ * WS, 256>>>(scores);

    // 5) attn = P @ V
    gemm_tc<<<dim3(1, WS / BM, NZ), 256>>>(
        scores, nullptr, nullptr, WS, WS, WS, 0, 0,
        qkv + 2 * CDIM, 3 * CDIM, 0, attn, CDIM, nullptr, nullptr,
        WS, HDIM, WS, 1.f, 0, 0,
        (long)WS * WS * HEADS, (long)WS * WS,
        (long)WS * 3 * CDIM, HDIM,
        (long)WS * CDIM, HDIM);

    // 6) x1[(m+SHIFT)%N] = x[...] + attn@proj_w + proj_b
    gemm_tc<<<dim3(CDIM / BN, NTOK / BM, 1), 256>>>(
        attn, nullptr, nullptr, CDIM, CDIM, CDIM, 0, 0,
        proj_w, CDIM, 0, x1, CDIM, proj_b, x,
        NTOK, CDIM, CDIM, 1.f, 2, SHIFTK, 0, 0, 0, 0, 0, 0);

    // 7) mv branch
    ln_kernel<<<NTOK, 256>>>(x1, lnb, 0);
    gemm_tc<<<dim3(HID / BN, NTOK / BM, 1), 256>>>(
        lnb, mvn, mvc, CDIM, CDIM + MVD4, CDIM, MVD4, MVD4,
        mv_w1, HID, 0, h1, HID, mv_b1, nullptr,
        NTOK, HID, KCAT, 1.f, 1, 0, 0, 0, 0, 0, 0, 0);
    gemm_tc<<<dim3(CDIM / BN, NTOK / BM, 1), 256>>>(
        h1, nullptr, nullptr, HID, HID, HID, 0, 0,
        mv_w2, CDIM, 0, x2, CDIM, mv_b2, x1,
        NTOK, CDIM, HID, 1.f, 2, 0, 0, 0, 0, 0, 0, 0);

    // 8) mlp branch
    ln_kernel<<<NTOK, 256>>>(x2, lnb, 0);
    gemm_tc<<<dim3(HID / BN, NTOK / BM, 1), 256>>>(
        lnb, nullptr, nullptr, CDIM, CDIM, CDIM, 0, 0,
        mlp_w1, HID, 0, h1, HID, mlp_b1, nullptr,
        NTOK, HID, CDIM, 1.f, 1, 0, 0, 0, 0, 0, 0, 0);
    gemm_tc<<<dim3(CDIM / BN, NTOK / BM, 1), 256>>>(
        h1, nullptr, nullptr, HID, HID, HID, 0, 0,
        mlp_w2, CDIM, 0, out, CDIM, mlp_b2, x2,
        NTOK, CDIM, HID, 1.f, 2, 0, 0, 0, 0, 0, 0, 0);
}

// round 8
// speedup vs baseline: 1.4731x; 1.4731x over previous
#include <cuda_runtime.h>
#include <cuda_fp16.h>
#include <cstdint>

// ---------------------------------------------------------------------------
// Round 5b: fp16 mma.sync (m16n8k16, fp32 accumulate) + L2 band-swizzled CTA
// ordering. (Round 5 failed only on __floats2half2_rn signature — fixed.)
// ---------------------------------------------------------------------------

#define NTOK 16384
#define CDIM 1024
#define HEADS 16
#define HDIM 64
#define WS 512
#define SHIFTK 256
#define MVD4 4096
#define KCAT 9216
#define HID 4096
#define NZ 512

__device__ float g_lnx  [(long)NTOK * CDIM];
__device__ float g_qkv  [(long)NTOK * 3 * CDIM];
__device__ float g_scores[(long)NZ * WS * WS];
__device__ float g_attn [(long)NTOK * CDIM];
__device__ float g_x1   [(long)NTOK * CDIM];
__device__ float g_x2   [(long)NTOK * CDIM];
__device__ float g_lnb  [(long)NTOK * CDIM];
__device__ float g_h1   [(long)NTOK * HID];

// ---------------------------------------------------------------------------
__global__ __launch_bounds__(256) void ln_kernel(const float* __restrict__ in,
                                                 float* __restrict__ out,
                                                 int shift) {
    int row = blockIdx.x;
    int src = (row + shift) & (NTOK - 1);
    const float* p = in + (long)src * CDIM;
    int t = threadIdx.x;
    float v[4], s = 0.f, s2 = 0.f;
#pragma unroll
    for (int i = 0; i < 4; i++) {
        v[i] = p[t + i * 256];
        s += v[i]; s2 += v[i] * v[i];
    }
#pragma unroll
    for (int o = 16; o; o >>= 1) {
        s  += __shfl_xor_sync(~0u, s, o);
        s2 += __shfl_xor_sync(~0u, s2, o);
    }
    __shared__ float red0[8], red1[8];
    int wid = t >> 5, lid = t & 31;
    if (lid == 0) { red0[wid] = s; red1[wid] = s2; }
    __syncthreads();
    if (t < 32) {
        float a = (t < 8) ? red0[t] : 0.f;
        float b = (t < 8) ? red1[t] : 0.f;
#pragma unroll
        for (int o = 4; o; o >>= 1) {
            a += __shfl_xor_sync(~0u, a, o);
            b += __shfl_xor_sync(~0u, b, o);
        }
        if (t == 0) { red0[0] = a; red1[0] = b; }
    }
    __syncthreads();
    float mean = red0[0] * (1.f / CDIM);
    float var  = red1[0] * (1.f / CDIM) - mean * mean;
    float r = rsqrtf(var + 1e-6f);
    float* q = out + (long)row * CDIM;
#pragma unroll
    for (int i = 0; i < 4; i++) q[t + i * 256] = (v[i] - mean) * r;
}

__global__ __launch_bounds__(256) void softmax_kernel(float* __restrict__ sc) {
    float* p = sc + (long)blockIdx.x * WS;
    int t = threadIdx.x;
    float a = p[t], b = p[t + 256];
    float mx = fmaxf(a, b);
    __shared__ float red[8];
    int wid = t >> 5, lid = t & 31;
#pragma unroll
    for (int o = 16; o; o >>= 1) mx = fmaxf(mx, __shfl_xor_sync(~0u, mx, o));
    if (lid == 0) red[wid] = mx;
    __syncthreads();
    if (t < 32) {
        float v = (t < 8) ? red[t] : -1e30f;
#pragma unroll
        for (int o = 4; o; o >>= 1) v = fmaxf(v, __shfl_xor_sync(~0u, v, o));
        if (t == 0) red[0] = v;
    }
    __syncthreads();
    mx = red[0];
    float ea = __expf(a - mx), eb = __expf(b - mx);
    float sum = ea + eb;
#pragma unroll
    for (int o = 16; o; o >>= 1) sum += __shfl_xor_sync(~0u, sum, o);
    __shared__ float red2[8];
    if (lid == 0) red2[wid] = sum;
    __syncthreads();
    if (t < 32) {
        float v = (t < 8) ? red2[t] : 0.f;
#pragma unroll
        for (int o = 4; o; o >>= 1) v += __shfl_xor_sync(~0u, v, o);
        if (t == 0) red2[0] = v;
    }
    __syncthreads();
    float inv = __frcp_rn(red2[0]);
    p[t] = ea * inv;
    p[t + 256] = eb * inv;
}

__device__ __forceinline__ float gelu_tanh(float v) {
    return 0.5f * v * (1.f + tanhf(0.7978845608028654f * (v + 0.044715f * v * v * v)));
}

__device__ __forceinline__ unsigned h2(float a, float b) {
    __half2 h = __floats2half2_rn(a, b);
    return *(unsigned*)&h;
}

#define MMA_F16(c, a0, a1, a2, a3, b0, b1)                                    \
    asm volatile("mma.sync.aligned.m16n8k16.row.col.f32.f16.f16.f32 "         \
                 "{%0,%1,%2,%3},{%4,%5,%6,%7},{%8,%9},{%0,%1,%2,%3};"         \
                 : "+f"((c)[0]), "+f"((c)[1]), "+f"((c)[2]), "+f"((c)[3])     \
                 : "r"(a0), "r"(a1), "r"(a2), "r"(a3), "r"(b0), "r"(b1))

// ---------------------------------------------------------------------------
// fp16 tensor-core GEMM, double-buffered SMEM, 1 barrier/iter, band-swizzled
// CTA order. BM=BN=128, BK=32 (halves), 256 threads (2x4 warps), warp 64x32.
// SMEM rows: 16 half2 words, stored as pairs (v,v+4)->(2v,2v+1) per k16 step
// so each fragment is one LDS.64; row stride 20 words.
// ---------------------------------------------------------------------------
#define BM 128
#define BN 128
#define BKH 32
#define SROW 20

__global__ __launch_bounds__(256, 2) void gemm_h(
    const float* __restrict__ A0, const float* __restrict__ A1,
    const float* __restrict__ A2, int kb1, int kb2,
    int lda0, int lda1, int lda2,
    const float* __restrict__ B, int ldb, int btrans,
    float* __restrict__ C, int ldc,
    const float* __restrict__ bias, const float* __restrict__ resid,
    int N, int K, float alpha, int epi, int rowShift, int bandw,
    long aZw, long aZh, long bZw, long bZh, long cZw, long cZh)
{
    __shared__ __align__(16) unsigned As[2][BM * SROW];
    __shared__ __align__(16) unsigned Bs[2][BN * SROW];

    const int z = blockIdx.z, w = z >> 4, hh = z & 15;
    const float* Ab = A0 + (long)w * aZw + (long)hh * aZh;
    const float* Bb = B  + (long)w * bZw + (long)hh * bZh;
    float*       Cb = C  + (long)w * cZw + (long)hh * cZh;

    // band-swizzled CTA remap: within a band of `bandw` N-tiles, M varies
    // fastest, keeping the band's weight panel L2-resident.
    int gx = gridDim.x, gy = gridDim.y;
    int id = blockIdx.y * gx + blockIdx.x;
    int per = bandw * gy;
    int band = id / per, rem = id - band * per;
    int bx = band * bandw + (rem % bandw);
    int by = rem / bandw;

    const int tid = threadIdx.x, lane = tid & 31, wid = tid >> 5;
    const int wm = wid >> 2, wn = wid & 3;
    const int g = lane >> 2, t4 = lane & 3;
    const int m0 = by * BM, n0 = bx * BN;

    float acc[4][4][4];
#pragma unroll
    for (int i = 0; i < 4; i++)
#pragma unroll
        for (int j = 0; j < 4; j++)
#pragma unroll
            for (int r = 0; r < 4; r++) acc[i][j][r] = 0.f;

    const int aM = tid >> 1;            // 0..127 row
    const int aS = tid & 1;             // k16 step owned
    const int bn0i = tid & 127;         // B-normal: col
    const int bS = tid >> 7;            // B-normal: step owned

    unsigned sa[8], sb[8];              // 8 half2 words (one k16 step)

    auto LOAD = [&](int k0) {
        {   // A: 16 consecutive k floats of row m0+aM, step aS
            int gk = k0 + aS * 16;
            const float* p;
            if (gk < kb1)      p = Ab + (long)(m0 + aM) * lda0 + gk;
            else if (gk < kb2) p = A1 + (long)(m0 + aM) * lda1 + (gk - kb1);
            else               p = A2 + (long)(m0 + aM) * lda2 + (gk - kb2);
            float4 f0 = *(const float4*)p;
            float4 f1 = *(const float4*)(p + 4);
            float4 f2 = *(const float4*)(p + 8);
            float4 f3 = *(const float4*)(p + 12);
            sa[0] = h2(f0.x, f0.y); sa[1] = h2(f0.z, f0.w);
            sa[2] = h2(f1.x, f1.y); sa[3] = h2(f1.z, f1.w);
            sa[4] = h2(f2.x, f2.y); sa[5] = h2(f2.z, f2.w);
            sa[6] = h2(f3.x, f3.y); sa[7] = h2(f3.z, f3.w);
        }
        if (btrans) {                   // B(k,n) at Bb[n*ldb+k]
            const float* p = Bb + (long)(n0 + aM) * ldb + k0 + aS * 16;
            float4 f0 = *(const float4*)p;
            float4 f1 = *(const float4*)(p + 4);
            float4 f2 = *(const float4*)(p + 8);
            float4 f3 = *(const float4*)(p + 12);
            sb[0] = h2(f0.x, f0.y); sb[1] = h2(f0.z, f0.w);
            sb[2] = h2(f1.x, f1.y); sb[3] = h2(f1.z, f1.w);
            sb[4] = h2(f2.x, f2.y); sb[5] = h2(f2.z, f2.w);
            sb[6] = h2(f3.x, f3.y); sb[7] = h2(f3.z, f3.w);
        } else {                        // B(k,n) at Bb[k*ldb+n]
            int gn = n0 + bn0i;
            int ks = k0 + bS * 16;
            float v[16];
#pragma unroll
            for (int r = 0; r < 16; r++)
                v[r] = (gn < N) ? Bb[(long)(ks + r) * ldb + gn] : 0.f;
#pragma unroll
            for (int j = 0; j < 8; j++) sb[j] = h2(v[2 * j], v[2 * j + 1]);
        }
    };

    auto STORE = [&](unsigned* Ad, unsigned* Bd) {
        unsigned* ap = Ad + aM * SROW + aS * 8;
#pragma unroll
        for (int j = 0; j < 4; j++)
            *(uint2*)(ap + 2 * j) = make_uint2(sa[j], sa[j + 4]);
        if (btrans) {
            unsigned* bp = Bd + aM * SROW + aS * 8;
#pragma unroll
            for (int j = 0; j < 4; j++)
                *(uint2*)(bp + 2 * j) = make_uint2(sb[j], sb[j + 4]);
        } else {
            unsigned* bp = Bd + bn0i * SROW + bS * 8;
#pragma unroll
            for (int j = 0; j < 4; j++)
                *(uint2*)(bp + 2 * j) = make_uint2(sb[j], sb[j + 4]);
        }
    };

    auto COMPUTE = [&](const unsigned* Ad, const unsigned* Bd) {
#pragma unroll
        for (int s = 0; s < 2; s++) {
            uint2 bf[4];
#pragma unroll
            for (int j = 0; j < 4; j++)
                bf[j] = *(const uint2*)&Bd[(wn * 32 + j * 8 + g) * SROW + s * 8 + 2 * t4];
#pragma unroll
            for (int i = 0; i < 4; i++) {
                int r = wm * 64 + i * 16 + g;
                uint2 lo = *(const uint2*)&Ad[r * SROW + s * 8 + 2 * t4];
                uint2 hi = *(const uint2*)&Ad[(r + 8) * SROW + s * 8 + 2 * t4];
#pragma unroll
                for (int j = 0; j < 4; j++)
                    MMA_F16(acc[i][j], lo.x, hi.x, lo.y, hi.y, bf[j].x, bf[j].y);
            }
        }
    };

    const int T = K / BKH;
    LOAD(0);
    STORE(As[0], Bs[0]);
    if (T > 1) LOAD(BKH);
    __syncthreads();
    for (int t = 0; t < T; t++) {
        int cur = t & 1;
        if (t + 1 < T) STORE(As[cur ^ 1], Bs[cur ^ 1]);   // regs hold tile t+1
        if (t + 2 < T) LOAD((t + 2) * BKH);
        COMPUTE(As[cur], Bs[cur]);
        __syncthreads();
    }

    // ---- epilogue ----
#pragma unroll
    for (int i = 0; i < 4; i++) {
        int mr = m0 + wm * 64 + i * 16 + g;
        int r0 = rowShift ? ((mr + rowShift) & (NTOK - 1)) : mr;
        int r1 = rowShift ? ((mr + 8 + rowShift) & (NTOK - 1)) : (mr + 8);
#pragma unroll
        for (int j = 0; j < 4; j++) {
            int col = n0 + wn * 32 + j * 8 + (t4 << 1);
            if (col >= N) continue;
            float b0 = bias ? bias[col]     : 0.f;
            float b1 = bias ? bias[col + 1] : 0.f;
            float v00 = acc[i][j][0] * alpha + b0;
            float v01 = acc[i][j][1] * alpha + b1;
            float v10 = acc[i][j][2] * alpha + b0;
            float v11 = acc[i][j][3] * alpha + b1;
            if (epi == 1) {
                v00 = gelu_tanh(v00); v01 = gelu_tanh(v01);
                v10 = gelu_tanh(v10); v11 = gelu_tanh(v11);
            } else if (epi == 2) {
                const float* q0 = resid + (long)r0 * ldc + col;
                const float* q1 = resid + (long)r1 * ldc + col;
                v00 += q0[0]; v01 += q0[1];
                v10 += q1[0]; v11 += q1[1];
            }
            *(float2*)(Cb + (long)r0 * ldc + col) = make_float2(v00, v01);
            *(float2*)(Cb + (long)r1 * ldc + col) = make_float2(v10, v11);
        }
    }
}

// ---------------------------------------------------------------------------
extern "C" void kernel_launch(void* const* d_in, const int* in_sizes, int n_in,
                              void* d_out, int out_size) {
    const float* x      = (const float*)d_in[0];
    const float* mvn    = (const float*)d_in[1];
    const float* mvc    = (const float*)d_in[2];
    const float* qkv_w  = (const float*)d_in[3];
    const float* qkv_b  = (const float*)d_in[4];
    const float* proj_w = (const float*)d_in[5];
    const float* proj_b = (const float*)d_in[6];
    const float* mv_w1  = (const float*)d_in[7];
    const float* mv_b1  = (const float*)d_in[8];
    const float* mv_w2  = (const float*)d_in[9];
    const float* mv_b2  = (const float*)d_in[10];
    const float* mlp_w1 = (const float*)d_in[11];
    const float* mlp_b1 = (const float*)d_in[12];
    const float* mlp_w2 = (const float*)d_in[13];
    const float* mlp_b2 = (const float*)d_in[14];
    float* out = (float*)d_out;

    float *lnx, *qkv, *scores, *attn, *x1, *x2, *lnb, *h1;
    cudaGetSymbolAddress((void**)&lnx,    g_lnx);
    cudaGetSymbolAddress((void**)&qkv,    g_qkv);
    cudaGetSymbolAddress((void**)&scores, g_scores);
    cudaGetSymbolAddress((void**)&attn,   g_attn);
    cudaGetSymbolAddress((void**)&x1,     g_x1);
    cudaGetSymbolAddress((void**)&x2,     g_x2);
    cudaGetSymbolAddress((void**)&lnb,    g_lnb);
    cudaGetSymbolAddress((void**)&h1,     g_h1);

    // 1) lnx[j] = LN(x[(j+SHIFT)%N])
    ln_kernel<<<NTOK, 256>>>(x, lnx, SHIFTK);

    // 2) qkv = lnx @ qkv_w + qkv_b
    gemm_h<<<dim3(3 * CDIM / BN, NTOK / BM, 1), 256>>>(
        lnx, nullptr, nullptr, CDIM, CDIM, CDIM, 0, 0,
        qkv_w, 3 * CDIM, 0, qkv, 3 * CDIM, qkv_b, nullptr,
        3 * CDIM, CDIM, 1.f, 0, 0, 8, 0, 0, 0, 0, 0, 0);

    // 3) scores = Q K^T / 8 per (window, head)
    gemm_h<<<dim3(WS / BN, WS / BM, NZ), 256>>>(
        qkv, nullptr, nullptr, CDIM * 4, CDIM * 4, 3 * CDIM, 0, 0,
        qkv + CDIM, 3 * CDIM, 1, scores, WS, nullptr, nullptr,
        WS, HDIM, 0.125f, 0, 0, 4,
        (long)WS * 3 * CDIM, HDIM,
        (long)WS * 3 * CDIM, HDIM,
        (long)WS * WS * HEADS, (long)WS * WS);

    // 4) softmax
    softmax_kernel<<<NZ * WS, 256>>>(scores);

    // 5) attn = P @ V
    gemm_h<<<dim3(1, WS / BM, NZ), 256>>>(
        scores, nullptr, nullptr, WS * 2, WS * 2, WS, 0, 0,
        qkv + 2 * CDIM, 3 * CDIM, 0, attn, CDIM, nullptr, nullptr,
        HDIM, WS, 1.f, 0, 0, 1,
        (long)WS * WS * HEADS, (long)WS * WS,
        (long)WS * 3 * CDIM, HDIM,
        (long)WS * CDIM, HDIM);

    // 6) x1[(m+SHIFT)%N] = x[...] + attn@proj_w + proj_b
    gemm_h<<<dim3(CDIM / BN, NTOK / BM, 1), 256>>>(
        attn, nullptr, nullptr, CDIM, CDIM, CDIM, 0, 0,
        proj_w, CDIM, 0, x1, CDIM, proj_b, x,
        CDIM, CDIM, 1.f, 2, SHIFTK, 8, 0, 0, 0, 0, 0, 0);

    // 7) mv branch
    ln_kernel<<<NTOK, 256>>>(x1, lnb, 0);
    gemm_h<<<dim3(HID / BN, NTOK / BM, 1), 256>>>(
        lnb, mvn, mvc, CDIM, CDIM + MVD4, CDIM, MVD4, MVD4,
        mv_w1, HID, 0, h1, HID, mv_b1, nullptr,
        HID, KCAT, 1.f, 1, 0, 8, 0, 0, 0, 0, 0, 0);
    gemm_h<<<dim3(CDIM / BN, NTOK / BM, 1), 256>>>(
        h1, nullptr, nullptr, HID, HID, HID, 0, 0,
        mv_w2, CDIM, 0, x2, CDIM, mv_b2, x1,
        CDIM, HID, 1.f, 2, 0, 8, 0, 0, 0, 0, 0, 0);

    // 8) mlp branch
    ln_kernel<<<NTOK, 256>>>(x2, lnb, 0);
    gemm_h<<<dim3(HID / BN, NTOK / BM, 1), 256>>>(
        lnb, nullptr, nullptr, CDIM, CDIM, CDIM, 0, 0,
        mlp_w1, HID, 0, h1, HID, mlp_b1, nullptr,
        HID, CDIM, 1.f, 1, 0, 8, 0, 0, 0, 0, 0, 0);
    gemm_h<<<dim3(CDIM / BN, NTOK / BM, 1), 256>>>(
        h1, nullptr, nullptr, HID, HID, HID, 0, 0,
        mlp_w2, CDIM, 0, out, CDIM, mlp_b2, x2,
        CDIM, HID, 1.f, 2, 0, 8, 0, 0, 0, 0, 0, 0);
}